// round 2
// baseline (speedup 1.0000x reference)
#include <cuda_runtime.h>
#include <cstdint>

// Problem constants
#define HW 16384          // 128*128
#define NB 4              // x batches
#define NG 4              // groups
#define CG 16             // channels per group
#define K2 9

// Scratch (allocation-free: __device__ globals)
__device__ __align__(16) float g_z[NB * 80 * HW];          // 5 convs x 16ch
__device__ __align__(16) float g_off[NB * NG * 18 * HW];   // per-group offsets
__device__ __align__(16) float g_mask[NB * K2 * HW];       // sigmoided mask

// ---------------------------------------------------------------------------
// Kernel 1: five 3x3 convs (16->16 ch, pad 1) on x[:, :16].
// grid (8, 8, NB*5), block 64.  Tile 16x16, each thread computes 4 px (along w)
// for all 16 out channels of one conv.  Weights + input tile staged in smem.
// ---------------------------------------------------------------------------
__global__ __launch_bounds__(64) void conv3x3_kernel(
    const float* __restrict__ x,
    const float* __restrict__ mask_pw,   // (16,16,3,3)
    const float* __restrict__ off_pw)    // (4,16,16,3,3)
{
    __shared__ float s_in[16 * 18 * 18];   // [ic][18][18]
    __shared__ float s_w[16 * 16 * 9];     // [oc][ic][9]

    const int bz = blockIdx.z;
    const int j  = bz % 5;        // 0 = mask conv, 1..4 = offset conv g
    const int b  = bz / 5;
    const int h0 = blockIdx.y * 16;
    const int w0 = blockIdx.x * 16;
    const int tid = threadIdx.x;

    const float* xb = x + (size_t)b * 64 * HW;
    for (int idx = tid; idx < 16 * 18 * 18; idx += 64) {
        int ic  = idx / 324;
        int rem = idx - ic * 324;
        int ly  = rem / 18;
        int lx  = rem - ly * 18;
        int gy = h0 - 1 + ly;
        int gx = w0 - 1 + lx;
        float v = 0.f;
        if ((unsigned)gy < 128u && (unsigned)gx < 128u)
            v = xb[ic * HW + gy * 128 + gx];
        s_in[idx] = v;
    }
    const float* wsrc = (j == 0) ? mask_pw : (off_pw + (j - 1) * 2304);
    for (int idx = tid; idx < 2304; idx += 64) s_w[idx] = wsrc[idx];
    __syncthreads();

    const int r  = tid >> 2;         // row in tile 0..15
    const int c0 = (tid & 3) * 4;    // col base 0,4,8,12

    float acc[16][4];
#pragma unroll
    for (int oc = 0; oc < 16; oc++)
#pragma unroll
        for (int p = 0; p < 4; p++) acc[oc][p] = 0.f;

#pragma unroll 1
    for (int ic = 0; ic < 16; ic++) {
        float v[18];
        const float* sp = s_in + ic * 324 + r * 18 + c0;
#pragma unroll
        for (int dy = 0; dy < 3; dy++)
#pragma unroll
            for (int dx = 0; dx < 6; dx++)
                v[dy * 6 + dx] = sp[dy * 18 + dx];

        const float* wp = s_w + ic * 9;
#pragma unroll
        for (int oc = 0; oc < 16; oc++) {
#pragma unroll
            for (int t = 0; t < 9; t++) {
                float wv = wp[oc * 144 + t];
                int dy = t / 3, dx = t % 3;
#pragma unroll
                for (int p = 0; p < 4; p++)
                    acc[oc][p] = fmaf(wv, v[dy * 6 + dx + p], acc[oc][p]);
            }
        }
    }

    const int ho = h0 + r;
    float* zp = g_z + ((size_t)(b * 80 + j * 16)) * HW + ho * 128 + w0 + c0;
#pragma unroll
    for (int oc = 0; oc < 16; oc++) {
        float4 o = make_float4(acc[oc][0], acc[oc][1], acc[oc][2], acc[oc][3]);
        *reinterpret_cast<float4*>(zp + (size_t)oc * HW) = o;
    }
}

// ---------------------------------------------------------------------------
// Kernel 2: 1x1 heads.  out[o] = W[o,0:16] . z_head + W[o,16:64] . x[16:64] + b
// MASK head (NO=9) applies sigmoid -> g_mask.  Offset heads (NO=18) -> g_off.
// Each thread handles 2 pixels (float2).
// ---------------------------------------------------------------------------
template <int NO, bool MASK>
__global__ __launch_bounds__(128) void head_kernel(
    const float* __restrict__ x,
    const float* __restrict__ wmat,
    const float* __restrict__ bias)
{
    __shared__ float s_w[NO * 64];

    const int slice = blockIdx.y;            // MASK: b;  else b*4+g
    const int b = MASK ? slice : (slice >> 2);
    const int m = MASK ? 0 : ((slice & 3) + 1);   // conv-head index in g_z
    const float* wsrc = MASK ? wmat : (wmat + (slice & 3) * NO * 64);
    for (int i = threadIdx.x; i < NO * 64; i += 128) s_w[i] = wsrc[i];
    __syncthreads();

    const int px2 = blockIdx.x * 128 + threadIdx.x;
    const int px  = px2 * 2;

    float2 acc[NO];
#pragma unroll
    for (int o = 0; o < NO; o++) acc[o] = make_float2(0.f, 0.f);

    const float* zb = g_z + (size_t)(b * 80 + m * 16) * HW + px;
    const float* xb = x   + (size_t)(b * 64 + 16)     * HW + px;

#pragma unroll 8
    for (int c = 0; c < 16; c++) {
        float2 v = *reinterpret_cast<const float2*>(zb + (size_t)c * HW);
#pragma unroll
        for (int o = 0; o < NO; o++) {
            float wv = s_w[o * 64 + c];
            acc[o].x = fmaf(wv, v.x, acc[o].x);
            acc[o].y = fmaf(wv, v.y, acc[o].y);
        }
    }
#pragma unroll 8
    for (int c = 0; c < 48; c++) {
        float2 v = *reinterpret_cast<const float2*>(xb + (size_t)c * HW);
#pragma unroll
        for (int o = 0; o < NO; o++) {
            float wv = s_w[o * 64 + 16 + c];
            acc[o].x = fmaf(wv, v.x, acc[o].x);
            acc[o].y = fmaf(wv, v.y, acc[o].y);
        }
    }

    if (MASK) {
        float* mp = g_mask + (size_t)b * 9 * HW + px;
#pragma unroll
        for (int o = 0; o < NO; o++) {
            float bb = bias[o];
            float sx = 1.f / (1.f + __expf(-(acc[o].x + bb)));
            float sy = 1.f / (1.f + __expf(-(acc[o].y + bb)));
            *reinterpret_cast<float2*>(mp + (size_t)o * HW) = make_float2(sx, sy);
        }
    } else {
        float* op = g_off + (size_t)slice * 18 * HW + px;
        const float* bs = bias + (slice & 3) * 18;
#pragma unroll
        for (int o = 0; o < NO; o++) {
            float bb = bs[o];
            *reinterpret_cast<float2*>(op + (size_t)o * HW) =
                make_float2(acc[o].x + bb, acc[o].y + bb);
        }
    }
}

// ---------------------------------------------------------------------------
// Kernel 3: modulated deformable bilinear sampling.
// Thread handles (b, g, h, 2 adjacent w), loops k2=9 taps x 16 channels,
// sampling both y1[b] and y2[b] group slices (32 outputs per tap-pixel).
// Work = 4*4*128*64 = 131072 threads exactly.
// ---------------------------------------------------------------------------
__global__ __launch_bounds__(256) void sample_kernel(
    const float* __restrict__ y, float* __restrict__ out)
{
    int idx = blockIdx.x * 256 + threadIdx.x;
    if (idx >= NB * NG * 128 * 64) return;
    const int w2 = idx & 63;  idx >>= 6;
    const int h  = idx & 127; idx >>= 7;
    const int g  = idx & 3;
    const int b  = idx >> 2;
    const int w  = w2 * 2;
    const int px = h * 128 + w;

    const float* off = g_off + ((size_t)(b * 4 + g) * 18) * HW + px;
    const float* msk = g_mask + (size_t)b * 9 * HW + px;
    const float* y1  = y + (size_t)(b * 64 + g * 16) * HW;
    const float* y2  = y + (size_t)((b + 4) * 64 + g * 16) * HW;
    float* o1 = out + (size_t)(b * 64 + g * 16) * 9 * HW + h * 128 + w;
    float* o2 = out + (size_t)((b + 4) * 64 + g * 16) * 9 * HW + h * 128 + w;

    const int dil = 2 * g + 1;

#pragma unroll 1
    for (int k = 0; k < 9; k++) {
        const int ky = k / 3 - 1;
        const int kx = k % 3 - 1;
        const float basey = (float)(h + ky * dil);
        const float basex = (float)(w + kx * dil);

        int   ci[2][4];
        float cw[2][4];
#pragma unroll
        for (int p = 0; p < 2; p++) {
            float py  = basey + off[(2 * k) * HW + p];
            float pxx = basex + (float)p + off[(2 * k + 1) * HW + p];
            float m   = msk[k * HW + p];

            float fy0 = floorf(py);
            float fx0 = floorf(pxx);
            float wy = py - fy0;
            float wx = pxx - fx0;

            // validity per corner (reference semantics: unclipped float compare)
            bool vy0 = (fy0 >= 0.f)  && (fy0 <= 127.f);
            bool vy1 = (fy0 >= -1.f) && (fy0 <= 126.f);
            bool vx0 = (fx0 >= 0.f)  && (fx0 <= 127.f);
            bool vx1 = (fx0 >= -1.f) && (fx0 <= 126.f);

            int y0c = (int)fminf(fmaxf(fy0,       0.f), 127.f);
            int y1c = (int)fminf(fmaxf(fy0 + 1.f, 0.f), 127.f);
            int x0c = (int)fminf(fmaxf(fx0,       0.f), 127.f);
            int x1c = (int)fminf(fmaxf(fx0 + 1.f, 0.f), 127.f);

            float w00 = (1.f - wy) * (1.f - wx) * m; if (!(vy0 && vx0)) w00 = 0.f;
            float w01 = (1.f - wy) * wx        * m; if (!(vy0 && vx1)) w01 = 0.f;
            float w10 = wy        * (1.f - wx) * m; if (!(vy1 && vx0)) w10 = 0.f;
            float w11 = wy        * wx         * m; if (!(vy1 && vx1)) w11 = 0.f;

            ci[p][0] = y0c * 128 + x0c;  cw[p][0] = w00;
            ci[p][1] = y0c * 128 + x1c;  cw[p][1] = w01;
            ci[p][2] = y1c * 128 + x0c;  cw[p][2] = w10;
            ci[p][3] = y1c * 128 + x1c;  cw[p][3] = w11;
        }

#pragma unroll
        for (int c = 0; c < 16; c++) {
            const float* s1 = y1 + (size_t)c * HW;
            const float* s2 = y2 + (size_t)c * HW;

            float r1x = cw[0][0] * s1[ci[0][0]] + cw[0][1] * s1[ci[0][1]]
                      + cw[0][2] * s1[ci[0][2]] + cw[0][3] * s1[ci[0][3]];
            float r1y = cw[1][0] * s1[ci[1][0]] + cw[1][1] * s1[ci[1][1]]
                      + cw[1][2] * s1[ci[1][2]] + cw[1][3] * s1[ci[1][3]];
            float r2x = cw[0][0] * s2[ci[0][0]] + cw[0][1] * s2[ci[0][1]]
                      + cw[0][2] * s2[ci[0][2]] + cw[0][3] * s2[ci[0][3]];
            float r2y = cw[1][0] * s2[ci[1][0]] + cw[1][1] * s2[ci[1][1]]
                      + cw[1][2] * s2[ci[1][2]] + cw[1][3] * s2[ci[1][3]];

            *reinterpret_cast<float2*>(o1 + (size_t)(c * 9 + k) * HW) = make_float2(r1x, r1y);
            *reinterpret_cast<float2*>(o2 + (size_t)(c * 9 + k) * HW) = make_float2(r2x, r2y);
        }
    }
}

// ---------------------------------------------------------------------------
extern "C" void kernel_launch(void* const* d_in, const int* in_sizes, int n_in,
                              void* d_out, int out_size)
{
    // Defensive remap by element count (all sizes unique)
    const float *x = nullptr, *y = nullptr, *off_pw = nullptr, *off_w = nullptr,
                *off_b = nullptr, *mask_pw = nullptr, *mask_w = nullptr, *mask_b = nullptr;
    for (int i = 0; i < n_in; i++) {
        switch (in_sizes[i]) {
            case 4194304: x       = (const float*)d_in[i]; break;
            case 8388608: y       = (const float*)d_in[i]; break;
            case 9216:    off_pw  = (const float*)d_in[i]; break;
            case 4608:    off_w   = (const float*)d_in[i]; break;
            case 72:      off_b   = (const float*)d_in[i]; break;
            case 2304:    mask_pw = (const float*)d_in[i]; break;
            case 576:     mask_w  = (const float*)d_in[i]; break;
            case 9:       mask_b  = (const float*)d_in[i]; break;
            default: break;
        }
    }
    float* out = (float*)d_out;

    conv3x3_kernel<<<dim3(8, 8, NB * 5), 64>>>(x, mask_pw, off_pw);
    head_kernel<9,  true ><<<dim3(64, NB),      128>>>(x, mask_w, mask_b);
    head_kernel<18, false><<<dim3(64, NB * NG), 128>>>(x, off_w, off_b);
    sample_kernel<<<512, 256>>>(y, out);
}